// round 1
// baseline (speedup 1.0000x reference)
#include <cuda_runtime.h>
#include <cuda_bf16.h>
#include <cstdint>

#define NQ     10000
#define NCAM   6
#define NHEAD  8
#define DH     32
#define DIMS   256
#define SUMHW  5440
#define NLVL   4
#define NPTS   8

// ---------------- scratch (device globals: no allocation allowed) ----------------
__device__ float g_vproj [NCAM * SUMHW * DIMS];   // 33.4 MB
__device__ float g_off   [NQ * 512];              // offsets raw (pre-normalization)
__device__ float g_attw  [NQ * 256];              // logits -> softmaxed attw
__device__ float g_outcam[(size_t)NCAM * NQ * DIMS]; // 61.4 MB
__device__ float g_slots [NQ * DIMS];

// ---------------- generic fp32 GEMM: C[M,N] = A[M,256] @ W[256,N] + bias (+resid) ---
// block tile: 32 rows x 256 cols, 256 threads, each thread 8x4 micro-tile.
__global__ __launch_bounds__(256) void gemm_bias_kernel(
    const float* __restrict__ A, const float* __restrict__ W,
    const float* __restrict__ bias, const float* __restrict__ resid,
    float* __restrict__ C, int M, int N)
{
    const int K = 256;
    __shared__ float Ash[32][33];
    __shared__ float Wsh[32 * 256];

    int row0 = blockIdx.x * 32;
    int c0   = blockIdx.y * 256;
    int t    = threadIdx.x;
    int rg   = t >> 6;   // 0..3  (row group of 8)
    int cg   = t & 63;   // 0..63 (col group of 4)

    float acc[8][4];
#pragma unroll
    for (int i = 0; i < 8; i++)
#pragma unroll
        for (int j = 0; j < 4; j++) acc[i][j] = 0.f;

    for (int k0 = 0; k0 < K; k0 += 32) {
        // load A tile 32x32 (guarded rows)
        {
            int r  = t >> 3;
            int kq = (t & 7) * 4;
            int row = row0 + r;
            float4 av = make_float4(0.f, 0.f, 0.f, 0.f);
            if (row < M)
                av = *reinterpret_cast<const float4*>(A + (size_t)row * K + k0 + kq);
            Ash[r][kq + 0] = av.x; Ash[r][kq + 1] = av.y;
            Ash[r][kq + 2] = av.z; Ash[r][kq + 3] = av.w;
        }
        // load W tile 32x256
#pragma unroll
        for (int j = 0; j < 8; j++) {
            int idx4 = t + j * 256;          // 0..2047 (float4 index)
            int kk   = idx4 >> 6;
            int c4   = (idx4 & 63) * 4;
            float4 wv = *reinterpret_cast<const float4*>(
                W + (size_t)(k0 + kk) * N + c0 + c4);
            *reinterpret_cast<float4*>(&Wsh[kk * 256 + c4]) = wv;
        }
        __syncthreads();
#pragma unroll
        for (int kk = 0; kk < 32; kk++) {
            float4 wv = *reinterpret_cast<const float4*>(&Wsh[kk * 256 + cg * 4]);
#pragma unroll
            for (int i = 0; i < 8; i++) {
                float a0 = Ash[rg * 8 + i][kk];
                acc[i][0] = fmaf(a0, wv.x, acc[i][0]);
                acc[i][1] = fmaf(a0, wv.y, acc[i][1]);
                acc[i][2] = fmaf(a0, wv.z, acc[i][2]);
                acc[i][3] = fmaf(a0, wv.w, acc[i][3]);
            }
        }
        __syncthreads();
    }

    int col = c0 + cg * 4;
    float4 bv = *reinterpret_cast<const float4*>(bias + col);
#pragma unroll
    for (int i = 0; i < 8; i++) {
        int row = row0 + rg * 8 + i;
        if (row >= M) continue;
        float4 o;
        o.x = acc[i][0] + bv.x;
        o.y = acc[i][1] + bv.y;
        o.z = acc[i][2] + bv.z;
        o.w = acc[i][3] + bv.w;
        if (resid) {
            float4 rv = *reinterpret_cast<const float4*>(resid + (size_t)row * N + col);
            o.x += rv.x; o.y += rv.y; o.z += rv.z; o.w += rv.w;
        }
        *reinterpret_cast<float4*>(C + (size_t)row * N + col) = o;
    }
}

// ---------------- softmax over Lv*P = 32 per (q, head); warp per head -------------
__global__ __launch_bounds__(256) void softmax32_kernel(float* __restrict__ logits)
{
    int q    = blockIdx.x;
    int h    = threadIdx.x >> 5;
    int lane = threadIdx.x & 31;
    float v = logits[(size_t)q * 256 + h * 32 + lane];
    float m = v;
#pragma unroll
    for (int o = 16; o; o >>= 1) m = fmaxf(m, __shfl_xor_sync(0xffffffffu, m, o));
    float e = __expf(v - m);
    float s = e;
#pragma unroll
    for (int o = 16; o; o >>= 1) s += __shfl_xor_sync(0xffffffffu, s, o);
    logits[(size_t)q * 256 + h * 32 + lane] = e / s;
}

// ---------------- deformable sampling: block = (q, cam), warp = head --------------
__global__ __launch_bounds__(256) void sample_kernel(
    const float* __restrict__ ref,        // [cam, 1, nq, 4, 2]
    const int*   __restrict__ mask,       // [cam, 1, nq, 4]
    float*       __restrict__ outcam)     // [cam, nq, 256]
{
    const int LW[NLVL]     = {64, 32, 16, 8};
    const int LSTART[NLVL] = {0, 4096, 5120, 5376};

    int q = blockIdx.x;
    int c = blockIdx.y;
    const int* mrow = mask + ((size_t)c * NQ + q) * 4;
    if ((mrow[0] | mrow[1] | mrow[2] | mrow[3]) == 0) return;  // invalid cam: skipped downstream

    int t = threadIdx.x;
    int h = t >> 5, d = t & 31;

    float rx[4], ry[4];
    const float* refq = ref + ((size_t)c * NQ + q) * 8;
#pragma unroll
    for (int dd = 0; dd < 4; dd++) { rx[dd] = refq[dd * 2]; ry[dd] = refq[dd * 2 + 1]; }

    const float* offq = g_off  + (size_t)q * 512 + h * 64;   // (h*4+lvl)*8+p, x/y pairs
    const float* awq  = g_attw + (size_t)q * 256 + h * 32;

    float res = 0.f;
#pragma unroll
    for (int lvl = 0; lvl < NLVL; lvl++) {
        const int wdim = LW[lvl];
        const int hdim = wdim;  // square levels
        const float* vb = g_vproj + ((size_t)(c * SUMHW + LSTART[lvl])) * DIMS + h * DH + d;
#pragma unroll
        for (int p = 0; p < NPTS; p++) {
            float ox = offq[lvl * 16 + p * 2 + 0];
            float oy = offq[lvl * 16 + p * 2 + 1];
            int dd = p & 3;
            // loc*w - 0.5 == ref*w + off - 0.5 (normalization cancels)
            float x = fmaf(rx[dd], (float)wdim, ox) - 0.5f;
            float y = fmaf(ry[dd], (float)hdim, oy) - 0.5f;
            float xf = floorf(x), yf = floorf(y);
            float tx = x - xf, ty = y - yf;
            int ix = (int)xf, iy = (int)yf;
            int x0c = min(max(ix, 0), wdim - 1);
            int x1c = min(max(ix + 1, 0), wdim - 1);
            int y0c = min(max(iy, 0), hdim - 1);
            int y1c = min(max(iy + 1, 0), hdim - 1);
            bool vx0 = (ix >= 0) && (ix < wdim);
            bool vx1 = (ix >= -1) && (ix < wdim - 1);
            bool vy0 = (iy >= 0) && (iy < hdim);
            bool vy1 = (iy >= -1) && (iy < hdim - 1);
            float w00 = (vx0 && vy0) ? (1.f - tx) * (1.f - ty) : 0.f;
            float w01 = (vx1 && vy0) ? tx * (1.f - ty) : 0.f;
            float w10 = (vx0 && vy1) ? (1.f - tx) * ty : 0.f;
            float w11 = (vx1 && vy1) ? tx * ty : 0.f;
            float acc = 0.f;
            // weights uniform across the warp -> uniform branches, no divergence
            if (w00 != 0.f) acc = fmaf(w00, vb[(size_t)(y0c * wdim + x0c) * DIMS], acc);
            if (w01 != 0.f) acc = fmaf(w01, vb[(size_t)(y0c * wdim + x1c) * DIMS], acc);
            if (w10 != 0.f) acc = fmaf(w10, vb[(size_t)(y1c * wdim + x0c) * DIMS], acc);
            if (w11 != 0.f) acc = fmaf(w11, vb[(size_t)(y1c * wdim + x1c) * DIMS], acc);
            res = fmaf(awq[lvl * 8 + p], acc, res);
        }
    }
    outcam[((size_t)c * NQ + q) * DIMS + t] = res;
}

// ---------------- reduce over valid cameras -> slots ------------------------------
__global__ __launch_bounds__(256) void reduce_kernel(
    const int* __restrict__ mask)
{
    int q = blockIdx.x;
    int t = threadIdx.x;
    float s = 0.f;
    int cnt = 0;
#pragma unroll
    for (int c = 0; c < NCAM; c++) {
        const int* mrow = mask + ((size_t)c * NQ + q) * 4;
        if ((mrow[0] | mrow[1] | mrow[2] | mrow[3]) != 0) {
            cnt++;
            s += g_outcam[((size_t)c * NQ + q) * DIMS + t];
        }
    }
    g_slots[(size_t)q * DIMS + t] = s / (float)max(cnt, 1);
}

// ---------------- launcher --------------------------------------------------------
extern "C" void kernel_launch(void* const* d_in, const int* in_sizes, int n_in,
                              void* d_out, int out_size)
{
    const float* query   = (const float*)d_in[0];
    // d_in[1] = key (unused by the math)
    const float* value   = (const float*)d_in[2];   // [6,5440,1,256] contiguous
    const float* refp    = (const float*)d_in[3];   // [6,1,10000,4,2]
    const int*   mask    = (const int*)  d_in[4];   // [6,1,10000,4]
    const float* value_W = (const float*)d_in[7];
    const float* value_b = (const float*)d_in[8];
    const float* off_W   = (const float*)d_in[9];
    const float* off_b   = (const float*)d_in[10];
    const float* attw_W  = (const float*)d_in[11];
    const float* attw_b  = (const float*)d_in[12];
    const float* out_W   = (const float*)d_in[13];
    const float* out_b   = (const float*)d_in[14];

    float *p_vproj, *p_off, *p_attw, *p_outcam, *p_slots;
    cudaGetSymbolAddress((void**)&p_vproj,  g_vproj);
    cudaGetSymbolAddress((void**)&p_off,    g_off);
    cudaGetSymbolAddress((void**)&p_attw,   g_attw);
    cudaGetSymbolAddress((void**)&p_outcam, g_outcam);
    cudaGetSymbolAddress((void**)&p_slots,  g_slots);

    // 1) value projection: [32640,256] @ [256,256] + b
    gemm_bias_kernel<<<dim3((NCAM * SUMHW + 31) / 32, 1), 256>>>(
        value, value_W, value_b, nullptr, p_vproj, NCAM * SUMHW, 256);

    // 2) offsets: [10000,256] @ [256,512] + b  (camera-invariant)
    gemm_bias_kernel<<<dim3((NQ + 31) / 32, 2), 256>>>(
        query, off_W, off_b, nullptr, p_off, NQ, 512);

    // 3) attention logits: [10000,256] @ [256,256] + b, then per-(q,h) softmax
    gemm_bias_kernel<<<dim3((NQ + 31) / 32, 1), 256>>>(
        query, attw_W, attw_b, nullptr, p_attw, NQ, 256);
    softmax32_kernel<<<NQ, 256>>>(p_attw);

    // 4) deformable bilinear sampling per (q, cam)
    sample_kernel<<<dim3(NQ, NCAM), 256>>>(refp, mask, p_outcam);

    // 5) valid-camera mean
    reduce_kernel<<<NQ, 256>>>(mask);

    // 6) output projection + residual query
    gemm_bias_kernel<<<dim3((NQ + 31) / 32, 1), 256>>>(
        p_slots, out_W, out_b, query, (float*)d_out, NQ, 256);
}

// round 2
// speedup vs baseline: 2.4388x; 2.4388x over previous
#include <cuda_runtime.h>
#include <cuda_bf16.h>
#include <cstdint>

#define NQ     10000
#define NCAM   6
#define NHEAD  8
#define DH     32
#define DIMS   256
#define SUMHW  5440
#define NLVL   4
#define NPTS   8

// ---------------- scratch (device globals; allocation forbidden) -----------------
__device__ float         g_off  [NQ * 512];                  // offsets
__device__ float         g_attw [NQ * 256];                  // softmaxed attn weights
__device__ __nv_bfloat16 g_vb   [NCAM * NHEAD * SUMHW * DH]; // vproj, head-major, 16.7 MB
__device__ float         g_slots[NQ * DIMS];                 // per-query pooled features

// ---------------- fp32 GEMM: C[M,N] = A[M,256] @ W[256,N] + bias (+resid) --------
// 64x128 tile, 256 threads, 8x4 micro-tile. Optional bf16 head-major epilogue.
__global__ __launch_bounds__(256) void gemm_kernel(
    const float* __restrict__ A, const float* __restrict__ W,
    const float* __restrict__ bias, const float* __restrict__ resid,
    float* __restrict__ C, __nv_bfloat16* __restrict__ Cbf, int M, int N)
{
    __shared__ float Ash[32][68];   // [k][row], stride 68 keeps 16B alignment
    __shared__ float Wsh[32][128];

    const int t    = threadIdx.x;
    const int row0 = blockIdx.x * 64;
    const int c0   = blockIdx.y * 128;
    const int rg   = t >> 5;    // warp id = row group (8 rows)
    const int cgi  = t & 31;    // col group (4 cols)

    float acc[8][4];
#pragma unroll
    for (int i = 0; i < 8; i++)
#pragma unroll
        for (int j = 0; j < 4; j++) acc[i][j] = 0.f;

    for (int k0 = 0; k0 < 256; k0 += 32) {
        // A tile 64x32 -> transposed smem
        {
            int r  = t >> 3;
            int kq = (t & 7) * 4;
#pragma unroll
            for (int half = 0; half < 2; half++) {
                int row = row0 + r + half * 32;
                float4 av = make_float4(0.f, 0.f, 0.f, 0.f);
                if (row < M)
                    av = *reinterpret_cast<const float4*>(A + (size_t)row * 256 + k0 + kq);
                Ash[kq + 0][r + half * 32] = av.x;
                Ash[kq + 1][r + half * 32] = av.y;
                Ash[kq + 2][r + half * 32] = av.z;
                Ash[kq + 3][r + half * 32] = av.w;
            }
        }
        // W tile 32x128
#pragma unroll
        for (int j = 0; j < 4; j++) {
            int kk = (t >> 5) + j * 8;
            float4 wv = *reinterpret_cast<const float4*>(
                W + (size_t)(k0 + kk) * N + c0 + cgi * 4);
            *reinterpret_cast<float4*>(&Wsh[kk][cgi * 4]) = wv;
        }
        __syncthreads();
#pragma unroll
        for (int kk = 0; kk < 32; kk++) {
            float4 b4 = *reinterpret_cast<const float4*>(&Wsh[kk][cgi * 4]);
            float4 a0 = *reinterpret_cast<const float4*>(&Ash[kk][rg * 8]);     // broadcast
            float4 a1 = *reinterpret_cast<const float4*>(&Ash[kk][rg * 8 + 4]); // broadcast
            float ar[8] = {a0.x, a0.y, a0.z, a0.w, a1.x, a1.y, a1.z, a1.w};
#pragma unroll
            for (int i = 0; i < 8; i++) {
                acc[i][0] = fmaf(ar[i], b4.x, acc[i][0]);
                acc[i][1] = fmaf(ar[i], b4.y, acc[i][1]);
                acc[i][2] = fmaf(ar[i], b4.z, acc[i][2]);
                acc[i][3] = fmaf(ar[i], b4.w, acc[i][3]);
            }
        }
        __syncthreads();
    }

    const int col = c0 + cgi * 4;
    float4 bv = *reinterpret_cast<const float4*>(bias + col);
#pragma unroll
    for (int i = 0; i < 8; i++) {
        int row = row0 + rg * 8 + i;
        if (row >= M) continue;
        float4 o;
        o.x = acc[i][0] + bv.x;
        o.y = acc[i][1] + bv.y;
        o.z = acc[i][2] + bv.z;
        o.w = acc[i][3] + bv.w;
        if (Cbf) {
            // vproj epilogue: bf16, layout [cam][head][pos][32]
            int cam = row / SUMHW;
            int pos = row - cam * SUMHW;
            int h   = col >> 5;
            int ch  = col & 31;
            __nv_bfloat16* dst = Cbf + (((size_t)(cam * NHEAD + h) * SUMHW + pos) * DH + ch);
            __nv_bfloat162 v01 = __floats2bfloat162_rn(o.x, o.y);
            __nv_bfloat162 v23 = __floats2bfloat162_rn(o.z, o.w);
            uint2 pk;
            pk.x = *reinterpret_cast<uint32_t*>(&v01);
            pk.y = *reinterpret_cast<uint32_t*>(&v23);
            *reinterpret_cast<uint2*>(dst) = pk;
        } else {
            if (resid) {
                float4 rv = *reinterpret_cast<const float4*>(resid + (size_t)row * N + col);
                o.x += rv.x; o.y += rv.y; o.z += rv.z; o.w += rv.w;
            }
            *reinterpret_cast<float4*>(C + (size_t)row * N + col) = o;
        }
    }
}

// ---------------- softmax over 32 per (q, head) -----------------------------------
__global__ __launch_bounds__(256) void softmax32_kernel(float* __restrict__ logits)
{
    int q    = blockIdx.x;
    int h    = threadIdx.x >> 5;
    int lane = threadIdx.x & 31;
    float v = logits[(size_t)q * 256 + h * 32 + lane];
    float m = v;
#pragma unroll
    for (int o = 16; o; o >>= 1) m = fmaxf(m, __shfl_xor_sync(0xffffffffu, m, o));
    float e = __expf(v - m);
    float s = e;
#pragma unroll
    for (int o = 16; o; o >>= 1) s += __shfl_xor_sync(0xffffffffu, s, o);
    logits[(size_t)q * 256 + h * 32 + lane] = e / s;
}

// ---------------- fused deformable sampling + camera mean -------------------------
// block = q, warp = head. Lane layout: point p = lane>>2, channels cb = (lane&3)*8.
__global__ __launch_bounds__(256) void sample_fused_kernel(
    const float* __restrict__ ref,     // [cam, 1, nq, 4, 2]
    const int*   __restrict__ mask)    // [cam, 1, nq, 4]
{
    const int q    = blockIdx.x;
    const int t    = threadIdx.x;
    const int h    = t >> 5;
    const int lane = t & 31;
    const int p    = lane >> 2;        // 0..7 (point within level)
    const int cb   = (lane & 3) * 8;   // channel block
    const int dd   = p & 3;            // d-height index

    const int   LW[NLVL]     = {64, 32, 16, 8};
    const int   LSTART[NLVL] = {0, 4096, 5120, 5376};

    // per-lane per-level offsets and attention weights (camera-invariant)
    float ox[NLVL], oy[NLVL], aw[NLVL];
    {
        const float* offq = g_off  + (size_t)q * 512 + h * 64;
        const float* awq  = g_attw + (size_t)q * 256 + h * 32;
#pragma unroll
        for (int lvl = 0; lvl < NLVL; lvl++) {
            float2 o = *reinterpret_cast<const float2*>(offq + lvl * 16 + p * 2);
            ox[lvl] = o.x; oy[lvl] = o.y;
            aw[lvl] = awq[lvl * 8 + p];
        }
    }

    float acc[8];
#pragma unroll
    for (int i = 0; i < 8; i++) acc[i] = 0.f;
    int cnt = 0;

    for (int c = 0; c < NCAM; c++) {
        int4 m4 = *reinterpret_cast<const int4*>(mask + ((size_t)c * NQ + q) * 4);
        if ((m4.x | m4.y | m4.z | m4.w) == 0) continue;
        cnt++;
        float2 r2 = *reinterpret_cast<const float2*>(
            ref + ((size_t)c * NQ + q) * 8 + dd * 2);
        const float rx = r2.x, ry = r2.y;

#pragma unroll
        for (int lvl = 0; lvl < NLVL; lvl++) {
            const int wdim = LW[lvl];
            const float wf = (float)wdim;
            float x = fmaf(rx, wf, ox[lvl]) - 0.5f;
            float y = fmaf(ry, wf, oy[lvl]) - 0.5f;
            float xf = floorf(x), yf = floorf(y);
            float tx = x - xf, ty = y - yf;
            int ix = (int)xf, iy = (int)yf;
            int x0c = min(max(ix, 0), wdim - 1);
            int x1c = min(max(ix + 1, 0), wdim - 1);
            int y0c = min(max(iy, 0), wdim - 1);
            int y1c = min(max(iy + 1, 0), wdim - 1);
            bool vx0 = (ix >= 0) && (ix < wdim);
            bool vx1 = (ix >= -1) && (ix < wdim - 1);
            bool vy0 = (iy >= 0) && (iy < wdim);
            bool vy1 = (iy >= -1) && (iy < wdim - 1);
            float a = aw[lvl];
            float w00 = (vx0 && vy0) ? (1.f - tx) * (1.f - ty) * a : 0.f;
            float w01 = (vx1 && vy0) ? tx * (1.f - ty) * a : 0.f;
            float w10 = (vx0 && vy1) ? (1.f - tx) * ty * a : 0.f;
            float w11 = (vx1 && vy1) ? tx * ty * a : 0.f;

            const __nv_bfloat16* vb = g_vb +
                (((size_t)(c * NHEAD + h) * SUMHW + LSTART[lvl]) * DH) + cb;

            int i00 = (y0c * wdim + x0c) * DH;
            int i01 = (y0c * wdim + x1c) * DH;
            int i10 = (y1c * wdim + x0c) * DH;
            int i11 = (y1c * wdim + x1c) * DH;

#define CORNER(WGT, IDX)                                                         \
            if (WGT != 0.f) {                                                    \
                uint4 raw = *reinterpret_cast<const uint4*>(vb + (IDX));         \
                const __nv_bfloat162* h2 =                                       \
                    reinterpret_cast<const __nv_bfloat162*>(&raw);               \
                _Pragma("unroll")                                                \
                for (int j = 0; j < 4; j++) {                                    \
                    float2 f = __bfloat1622float2(h2[j]);                        \
                    acc[2*j]   = fmaf(WGT, f.x, acc[2*j]);                       \
                    acc[2*j+1] = fmaf(WGT, f.y, acc[2*j+1]);                     \
                }                                                                \
            }
            CORNER(w00, i00)
            CORNER(w01, i01)
            CORNER(w10, i10)
            CORNER(w11, i11)
#undef CORNER
        }
    }

    const float inv = 1.f / (float)max(cnt, 1);
#pragma unroll
    for (int i = 0; i < 8; i++) acc[i] *= inv;

    // reduce over the 8 points (lanes differing in bits 2..4)
#pragma unroll
    for (int s = 4; s < 32; s <<= 1)
#pragma unroll
        for (int i = 0; i < 8; i++)
            acc[i] += __shfl_xor_sync(0xffffffffu, acc[i], s);

    if (lane < 4) {
        float* dst = g_slots + (size_t)q * DIMS + h * DH + lane * 8;
        float4 o0 = make_float4(acc[0], acc[1], acc[2], acc[3]);
        float4 o1 = make_float4(acc[4], acc[5], acc[6], acc[7]);
        *reinterpret_cast<float4*>(dst)     = o0;
        *reinterpret_cast<float4*>(dst + 4) = o1;
    }
}

// ---------------- launcher --------------------------------------------------------
extern "C" void kernel_launch(void* const* d_in, const int* in_sizes, int n_in,
                              void* d_out, int out_size)
{
    const float* query   = (const float*)d_in[0];
    const float* value   = (const float*)d_in[2];   // [6,5440,1,256]
    const float* refp    = (const float*)d_in[3];   // [6,1,10000,4,2]
    const int*   mask    = (const int*)  d_in[4];   // [6,1,10000,4]
    const float* value_W = (const float*)d_in[7];
    const float* value_b = (const float*)d_in[8];
    const float* off_W   = (const float*)d_in[9];
    const float* off_b   = (const float*)d_in[10];
    const float* attw_W  = (const float*)d_in[11];
    const float* attw_b  = (const float*)d_in[12];
    const float* out_W   = (const float*)d_in[13];
    const float* out_b   = (const float*)d_in[14];

    float *p_off, *p_attw, *p_slots;
    __nv_bfloat16* p_vb;
    cudaGetSymbolAddress((void**)&p_off,   g_off);
    cudaGetSymbolAddress((void**)&p_attw,  g_attw);
    cudaGetSymbolAddress((void**)&p_vb,    g_vb);
    cudaGetSymbolAddress((void**)&p_slots, g_slots);

    // 1) value projection -> bf16 head-major scratch
    gemm_kernel<<<dim3((NCAM * SUMHW + 63) / 64, 2), 256>>>(
        value, value_W, value_b, nullptr, nullptr, p_vb, NCAM * SUMHW, 256);

    // 2) offsets (camera-invariant): [10000,256]@[256,512]
    gemm_kernel<<<dim3((NQ + 63) / 64, 4), 256>>>(
        query, off_W, off_b, nullptr, p_off, nullptr, NQ, 512);

    // 3) attention logits + softmax
    gemm_kernel<<<dim3((NQ + 63) / 64, 2), 256>>>(
        query, attw_W, attw_b, nullptr, p_attw, nullptr, NQ, 256);
    softmax32_kernel<<<NQ, 256>>>(p_attw);

    // 4) fused sampling over cameras + mean -> slots
    sample_fused_kernel<<<NQ, 256>>>(refp, mask);

    // 5) output projection + residual
    gemm_kernel<<<dim3((NQ + 63) / 64, 2), 256>>>(
        p_slots, out_W, out_b, query, (float*)d_out, nullptr, NQ, 256);
}

// round 3
// speedup vs baseline: 2.4924x; 1.0220x over previous
#include <cuda_runtime.h>
#include <cuda_bf16.h>
#include <cstdint>

#define NQ     10000
#define NCAM   6
#define NHEAD  8
#define DH     32
#define DIMS   256
#define SUMHW  5440
#define NLVL   4
#define NPTS   8

// ---------------- scratch (device globals; allocation forbidden) -----------------
__device__ __nv_bfloat16 g_value_bf[NCAM * SUMHW * DIMS];    // value in bf16
__device__ __nv_bfloat16 g_query_bf[NQ * DIMS];              // query in bf16
__device__ __nv_bfloat16 g_wt_val  [256 * 256];              // value_W^T bf16 [N][K]
__device__ __nv_bfloat16 g_wt_off  [512 * 256];
__device__ __nv_bfloat16 g_wt_attw [256 * 256];
__device__ __nv_bfloat16 g_wt_out  [256 * 256];
__device__ float         g_off  [NQ * 512];                  // offsets fp32
__device__ float         g_attw [NQ * 256];                  // softmaxed attn weights
__device__ __nv_bfloat16 g_vb   [NCAM * NHEAD * SUMHW * DH]; // vproj head-major bf16
__device__ __nv_bfloat16 g_slots_bf[NQ * DIMS];              // pooled features bf16

// ---------------- fp32 -> bf16 convert -------------------------------------------
__global__ __launch_bounds__(256) void f2bf_kernel(
    const float* __restrict__ A, __nv_bfloat16* __restrict__ B, int n4)
{
    int i = blockIdx.x * 256 + threadIdx.x;
    if (i >= n4) return;
    float4 v = reinterpret_cast<const float4*>(A)[i];
    __nv_bfloat162 a = __floats2bfloat162_rn(v.x, v.y);
    __nv_bfloat162 b = __floats2bfloat162_rn(v.z, v.w);
    uint2 pk;
    pk.x = *reinterpret_cast<uint32_t*>(&a);
    pk.y = *reinterpret_cast<uint32_t*>(&b);
    reinterpret_cast<uint2*>(B)[i] = pk;
}

// ---------------- W [K=256][N] fp32 -> Wt [N][K=256] bf16 ------------------------
__global__ __launch_bounds__(256) void wtrans_kernel(
    const float* __restrict__ W, __nv_bfloat16* __restrict__ Wt, int N)
{
    __shared__ float tile[32][33];
    int n0 = blockIdx.x * 32, k0 = blockIdx.y * 32;
    int tx = threadIdx.x & 31, ty = threadIdx.x >> 5;  // ty 0..7
#pragma unroll
    for (int i = ty; i < 32; i += 8)
        tile[i][tx] = W[(size_t)(k0 + i) * N + n0 + tx];
    __syncthreads();
#pragma unroll
    for (int i = ty; i < 32; i += 8)
        Wt[(size_t)(n0 + i) * 256 + k0 + tx] = __float2bfloat16(tile[tx][i]);
}

// ---------------- bf16 tensor-core GEMM: C[M,N] = A[M,256] @ Wt^T + bias ---------
// 128x64 block tile, 8 warps each 32x32, mma.sync m16n8k16. Smem stride 40 bf16
// (conflict-free ldmatrix). Epilogues: fp32 (+resid) | bf16 head-major vproj.
#define AST 40
__global__ __launch_bounds__(256) void mma_gemm_kernel(
    const __nv_bfloat16* __restrict__ A, const __nv_bfloat16* __restrict__ Wt,
    const float* __restrict__ bias, const float* __restrict__ resid,
    float* __restrict__ C, __nv_bfloat16* __restrict__ Cvb, int M, int N)
{
    __shared__ __nv_bfloat16 Ash[128 * AST];
    __shared__ __nv_bfloat16 Bsh[64 * AST];

    const int t = threadIdx.x;
    const int wid = t >> 5, lane = t & 31;
    const int wm = (wid & 3) * 32;
    const int wn = (wid >> 2) * 32;
    const int row0 = blockIdx.x * 128;
    const int col0 = blockIdx.y * 64;

    float acc[2][4][4];
#pragma unroll
    for (int a = 0; a < 2; a++)
#pragma unroll
        for (int b = 0; b < 4; b++)
#pragma unroll
            for (int c = 0; c < 4; c++) acc[a][b][c] = 0.f;

    const int a_row = lane & 15;
    const int a_col = (lane >> 4) * 8;
    const int b_row = (lane & 7) + ((lane >> 4) << 3);
    const int b_col = ((lane >> 3) & 1) * 8;

    for (int k0 = 0; k0 < 256; k0 += 32) {
        // A tile 128x32
        {
            int idx = t * 8;
            int r = idx >> 5, c = idx & 31;
#pragma unroll
            for (int half = 0; half < 2; half++) {
                int rr = r + half * 64;
                int grow = row0 + rr;
                uint4 v = make_uint4(0u, 0u, 0u, 0u);
                if (grow < M)
                    v = *reinterpret_cast<const uint4*>(A + (size_t)grow * 256 + k0 + c);
                *reinterpret_cast<uint4*>(Ash + rr * AST + c) = v;
            }
        }
        // B tile 64x32 from Wt[N][256]
        {
            int r = t >> 2, c = (t & 3) * 8;
            uint4 v = *reinterpret_cast<const uint4*>(Wt + (size_t)(col0 + r) * 256 + k0 + c);
            *reinterpret_cast<uint4*>(Bsh + r * AST + c) = v;
        }
        __syncthreads();
#pragma unroll
        for (int ks = 0; ks < 2; ks++) {
            uint32_t af[2][4], bfr[2][4];
#pragma unroll
            for (int mi = 0; mi < 2; mi++) {
                uint32_t addr = (uint32_t)__cvta_generic_to_shared(
                    Ash + (wm + mi * 16 + a_row) * AST + ks * 16 + a_col);
                asm volatile("ldmatrix.sync.aligned.m8n8.x4.shared.b16 {%0,%1,%2,%3}, [%4];"
                    : "=r"(af[mi][0]), "=r"(af[mi][1]), "=r"(af[mi][2]), "=r"(af[mi][3])
                    : "r"(addr));
            }
#pragma unroll
            for (int bi = 0; bi < 2; bi++) {
                uint32_t addr = (uint32_t)__cvta_generic_to_shared(
                    Bsh + (wn + bi * 16 + b_row) * AST + ks * 16 + b_col);
                asm volatile("ldmatrix.sync.aligned.m8n8.x4.shared.b16 {%0,%1,%2,%3}, [%4];"
                    : "=r"(bfr[bi][0]), "=r"(bfr[bi][1]), "=r"(bfr[bi][2]), "=r"(bfr[bi][3])
                    : "r"(addr));
            }
#pragma unroll
            for (int mi = 0; mi < 2; mi++)
#pragma unroll
                for (int ni = 0; ni < 4; ni++) {
                    uint32_t b0 = bfr[ni >> 1][(ni & 1) * 2];
                    uint32_t b1 = bfr[ni >> 1][(ni & 1) * 2 + 1];
                    asm volatile(
                        "mma.sync.aligned.m16n8k16.row.col.f32.bf16.bf16.f32 "
                        "{%0,%1,%2,%3}, {%4,%5,%6,%7}, {%8,%9}, {%0,%1,%2,%3};"
                        : "+f"(acc[mi][ni][0]), "+f"(acc[mi][ni][1]),
                          "+f"(acc[mi][ni][2]), "+f"(acc[mi][ni][3])
                        : "r"(af[mi][0]), "r"(af[mi][1]), "r"(af[mi][2]), "r"(af[mi][3]),
                          "r"(b0), "r"(b1));
                }
        }
        __syncthreads();
    }

    const int lrow = lane >> 2, lcol = (lane & 3) * 2;
#pragma unroll
    for (int mi = 0; mi < 2; mi++)
#pragma unroll
        for (int ni = 0; ni < 4; ni++)
#pragma unroll
            for (int half = 0; half < 2; half++) {
                int grow = row0 + wm + mi * 16 + lrow + half * 8;
                int gcol = col0 + wn + ni * 8 + lcol;
                if (grow >= M) continue;
                float v0 = acc[mi][ni][half * 2 + 0] + bias[gcol];
                float v1 = acc[mi][ni][half * 2 + 1] + bias[gcol + 1];
                if (Cvb) {
                    int cam = grow / SUMHW, pos = grow - cam * SUMHW;
                    int h = gcol >> 5, ch = gcol & 31;
                    __nv_bfloat162 p = __floats2bfloat162_rn(v0, v1);
                    *reinterpret_cast<__nv_bfloat162*>(
                        Cvb + (((size_t)(cam * NHEAD + h) * SUMHW + pos) * DH + ch)) = p;
                } else {
                    if (resid) {
                        v0 += resid[(size_t)grow * N + gcol];
                        v1 += resid[(size_t)grow * N + gcol + 1];
                    }
                    *reinterpret_cast<float2*>(C + (size_t)grow * N + gcol) =
                        make_float2(v0, v1);
                }
            }
}

// ---------------- softmax over 32 per (q, head) -----------------------------------
__global__ __launch_bounds__(256) void softmax32_kernel(float* __restrict__ logits)
{
    int q    = blockIdx.x;
    int h    = threadIdx.x >> 5;
    int lane = threadIdx.x & 31;
    float v = logits[(size_t)q * 256 + h * 32 + lane];
    float m = v;
#pragma unroll
    for (int o = 16; o; o >>= 1) m = fmaxf(m, __shfl_xor_sync(0xffffffffu, m, o));
    float e = __expf(v - m);
    float s = e;
#pragma unroll
    for (int o = 16; o; o >>= 1) s += __shfl_xor_sync(0xffffffffu, s, o);
    logits[(size_t)q * 256 + h * 32 + lane] = e / s;
}

// ---------------- fused deformable sampling + camera mean -------------------------
__global__ __launch_bounds__(256) void sample_fused_kernel(
    const float* __restrict__ ref,     // [cam, 1, nq, 4, 2]
    const int*   __restrict__ mask)    // [cam, 1, nq, 4]
{
    const int q    = blockIdx.x;
    const int t    = threadIdx.x;
    const int h    = t >> 5;
    const int lane = t & 31;
    const int p    = lane >> 2;        // 0..7
    const int cb   = (lane & 3) * 8;   // channel block
    const int dd   = p & 3;

    const int LW[NLVL]     = {64, 32, 16, 8};
    const int LSTART[NLVL] = {0, 4096, 5120, 5376};

    float ox[NLVL], oy[NLVL], aw[NLVL];
    {
        const float* offq = g_off  + (size_t)q * 512 + h * 64;
        const float* awq  = g_attw + (size_t)q * 256 + h * 32;
#pragma unroll
        for (int lvl = 0; lvl < NLVL; lvl++) {
            float2 o = *reinterpret_cast<const float2*>(offq + lvl * 16 + p * 2);
            ox[lvl] = o.x; oy[lvl] = o.y;
            aw[lvl] = awq[lvl * 8 + p];
        }
    }

    float acc[8];
#pragma unroll
    for (int i = 0; i < 8; i++) acc[i] = 0.f;
    int cnt = 0;

    for (int c = 0; c < NCAM; c++) {
        int4 m4 = *reinterpret_cast<const int4*>(mask + ((size_t)c * NQ + q) * 4);
        if ((m4.x | m4.y | m4.z | m4.w) == 0) continue;
        cnt++;
        float2 r2 = *reinterpret_cast<const float2*>(
            ref + ((size_t)c * NQ + q) * 8 + dd * 2);
        const float rx = r2.x, ry = r2.y;

#pragma unroll
        for (int lvl = 0; lvl < NLVL; lvl++) {
            const int wdim = LW[lvl];
            const float wf = (float)wdim;
            float x = fmaf(rx, wf, ox[lvl]) - 0.5f;
            float y = fmaf(ry, wf, oy[lvl]) - 0.5f;
            float xf = floorf(x), yf = floorf(y);
            float tx = x - xf, ty = y - yf;
            int ix = (int)xf, iy = (int)yf;
            int x0c = min(max(ix, 0), wdim - 1);
            int x1c = min(max(ix + 1, 0), wdim - 1);
            int y0c = min(max(iy, 0), wdim - 1);
            int y1c = min(max(iy + 1, 0), wdim - 1);
            bool vx0 = (ix >= 0) && (ix < wdim);
            bool vx1 = (ix >= -1) && (ix < wdim - 1);
            bool vy0 = (iy >= 0) && (iy < wdim);
            bool vy1 = (iy >= -1) && (iy < wdim - 1);
            float a = aw[lvl];
            float w00 = (vx0 && vy0) ? (1.f - tx) * (1.f - ty) * a : 0.f;
            float w01 = (vx1 && vy0) ? tx * (1.f - ty) * a : 0.f;
            float w10 = (vx0 && vy1) ? (1.f - tx) * ty * a : 0.f;
            float w11 = (vx1 && vy1) ? tx * ty * a : 0.f;

            const __nv_bfloat16* vb = g_vb +
                (((size_t)(c * NHEAD + h) * SUMHW + LSTART[lvl]) * DH) + cb;

            int i00 = (y0c * wdim + x0c) * DH;
            int i01 = (y0c * wdim + x1c) * DH;
            int i10 = (y1c * wdim + x0c) * DH;
            int i11 = (y1c * wdim + x1c) * DH;

#define CORNER(WGT, IDX)                                                         \
            if (WGT != 0.f) {                                                    \
                uint4 raw = *reinterpret_cast<const uint4*>(vb + (IDX));         \
                const __nv_bfloat162* h2 =                                       \
                    reinterpret_cast<const __nv_bfloat162*>(&raw);               \
                _Pragma("unroll")                                                \
                for (int j = 0; j < 4; j++) {                                    \
                    float2 f = __bfloat1622float2(h2[j]);                        \
                    acc[2*j]   = fmaf(WGT, f.x, acc[2*j]);                       \
                    acc[2*j+1] = fmaf(WGT, f.y, acc[2*j+1]);                     \
                }                                                                \
            }
            CORNER(w00, i00)
            CORNER(w01, i01)
            CORNER(w10, i10)
            CORNER(w11, i11)
#undef CORNER
        }
    }

    const float inv = 1.f / (float)max(cnt, 1);
#pragma unroll
    for (int i = 0; i < 8; i++) acc[i] *= inv;

#pragma unroll
    for (int s = 4; s < 32; s <<= 1)
#pragma unroll
        for (int i = 0; i < 8; i++)
            acc[i] += __shfl_xor_sync(0xffffffffu, acc[i], s);

    if (lane < 4) {
        __nv_bfloat162 p0 = __floats2bfloat162_rn(acc[0], acc[1]);
        __nv_bfloat162 p1 = __floats2bfloat162_rn(acc[2], acc[3]);
        __nv_bfloat162 p2 = __floats2bfloat162_rn(acc[4], acc[5]);
        __nv_bfloat162 p3 = __floats2bfloat162_rn(acc[6], acc[7]);
        uint4 pk;
        pk.x = *reinterpret_cast<uint32_t*>(&p0);
        pk.y = *reinterpret_cast<uint32_t*>(&p1);
        pk.z = *reinterpret_cast<uint32_t*>(&p2);
        pk.w = *reinterpret_cast<uint32_t*>(&p3);
        *reinterpret_cast<uint4*>(
            g_slots_bf + (size_t)q * DIMS + h * DH + (lane & 3) * 8) = pk;
    }
}

// ---------------- launcher --------------------------------------------------------
extern "C" void kernel_launch(void* const* d_in, const int* in_sizes, int n_in,
                              void* d_out, int out_size)
{
    const float* query   = (const float*)d_in[0];
    const float* value   = (const float*)d_in[2];
    const float* refp    = (const float*)d_in[3];
    const int*   mask    = (const int*)  d_in[4];
    const float* value_W = (const float*)d_in[7];
    const float* value_b = (const float*)d_in[8];
    const float* off_W   = (const float*)d_in[9];
    const float* off_b   = (const float*)d_in[10];
    const float* attw_W  = (const float*)d_in[11];
    const float* attw_b  = (const float*)d_in[12];
    const float* out_W   = (const float*)d_in[13];
    const float* out_b   = (const float*)d_in[14];

    __nv_bfloat16 *p_value_bf, *p_query_bf, *p_wt_val, *p_wt_off, *p_wt_attw,
                  *p_wt_out, *p_vb, *p_slots_bf;
    float *p_off, *p_attw;
    cudaGetSymbolAddress((void**)&p_value_bf, g_value_bf);
    cudaGetSymbolAddress((void**)&p_query_bf, g_query_bf);
    cudaGetSymbolAddress((void**)&p_wt_val,   g_wt_val);
    cudaGetSymbolAddress((void**)&p_wt_off,   g_wt_off);
    cudaGetSymbolAddress((void**)&p_wt_attw,  g_wt_attw);
    cudaGetSymbolAddress((void**)&p_wt_out,   g_wt_out);
    cudaGetSymbolAddress((void**)&p_vb,       g_vb);
    cudaGetSymbolAddress((void**)&p_slots_bf, g_slots_bf);
    cudaGetSymbolAddress((void**)&p_off,      g_off);
    cudaGetSymbolAddress((void**)&p_attw,     g_attw);

    // conversions
    f2bf_kernel<<<(NCAM * SUMHW * DIMS / 4 + 255) / 256, 256>>>(
        value, p_value_bf, NCAM * SUMHW * DIMS / 4);
    f2bf_kernel<<<(NQ * DIMS / 4 + 255) / 256, 256>>>(
        query, p_query_bf, NQ * DIMS / 4);
    wtrans_kernel<<<dim3(8, 8),  256>>>(value_W, p_wt_val, 256);
    wtrans_kernel<<<dim3(16, 8), 256>>>(off_W,   p_wt_off, 512);
    wtrans_kernel<<<dim3(8, 8),  256>>>(attw_W,  p_wt_attw, 256);
    wtrans_kernel<<<dim3(8, 8),  256>>>(out_W,   p_wt_out, 256);

    // 1) value projection -> bf16 head-major
    mma_gemm_kernel<<<dim3((NCAM * SUMHW + 127) / 128, 4), 256>>>(
        p_value_bf, p_wt_val, value_b, nullptr, nullptr, p_vb, NCAM * SUMHW, 256);

    // 2) offsets
    mma_gemm_kernel<<<dim3((NQ + 127) / 128, 8), 256>>>(
        p_query_bf, p_wt_off, off_b, nullptr, p_off, nullptr, NQ, 512);

    // 3) attention logits + softmax
    mma_gemm_kernel<<<dim3((NQ + 127) / 128, 4), 256>>>(
        p_query_bf, p_wt_attw, attw_b, nullptr, p_attw, nullptr, NQ, 256);
    softmax32_kernel<<<NQ, 256>>>(p_attw);

    // 4) fused sampling + camera mean -> bf16 slots
    sample_fused_kernel<<<NQ, 256>>>(refp, mask);

    // 5) output projection + residual
    mma_gemm_kernel<<<dim3((NQ + 127) / 128, 4), 256>>>(
        p_slots_bf, p_wt_out, out_b, query, (float*)d_out, nullptr, NQ, 256);
}

// round 4
// speedup vs baseline: 4.2570x; 1.7080x over previous
#include <cuda_runtime.h>
#include <cuda_bf16.h>
#include <cuda_fp16.h>
#include <cuda_fp8.h>
#include <cstdint>

#define NQ     10000
#define NCAM   6
#define NHEAD  8
#define DH     32
#define DIMS   256
#define SUMHW  5440
#define NLVL   4
#define NPTS   8

// ---------------- scratch (device globals; allocation forbidden) -----------------
__device__ __nv_bfloat16 g_value_bf[NCAM * SUMHW * DIMS];    // value in bf16
__device__ __nv_bfloat16 g_query_bf[NQ * DIMS];              // query in bf16
__device__ __nv_bfloat16 g_wt_val  [256 * 256];              // value_W^T bf16 [N][K]
__device__ __nv_bfloat16 g_wt_off  [512 * 256];
__device__ __nv_bfloat16 g_wt_attw [256 * 256];
__device__ __nv_bfloat16 g_wt_out  [256 * 256];
__device__ float         g_off  [NQ * 512];                  // offsets fp32
__device__ float         g_attw [NQ * 256];                  // raw attn logits
__device__ uint8_t       g_vb8  [NCAM * NHEAD * SUMHW * DH]; // vproj fp8 e4m3 (x16), 8.3MB
__device__ __nv_bfloat16 g_slots_bf[NQ * DIMS];              // pooled features bf16

// ---------------- fp32 -> bf16 convert -------------------------------------------
__global__ __launch_bounds__(256) void f2bf_kernel(
    const float* __restrict__ A, __nv_bfloat16* __restrict__ B, int n4)
{
    int i = blockIdx.x * 256 + threadIdx.x;
    if (i >= n4) return;
    float4 v = reinterpret_cast<const float4*>(A)[i];
    __nv_bfloat162 a = __floats2bfloat162_rn(v.x, v.y);
    __nv_bfloat162 b = __floats2bfloat162_rn(v.z, v.w);
    uint2 pk;
    pk.x = *reinterpret_cast<uint32_t*>(&a);
    pk.y = *reinterpret_cast<uint32_t*>(&b);
    reinterpret_cast<uint2*>(B)[i] = pk;
}

// ---------------- W [K=256][N] fp32 -> Wt [N][K=256] bf16 ------------------------
__global__ __launch_bounds__(256) void wtrans_kernel(
    const float* __restrict__ W, __nv_bfloat16* __restrict__ Wt, int N)
{
    __shared__ float tile[32][33];
    int n0 = blockIdx.x * 32, k0 = blockIdx.y * 32;
    int tx = threadIdx.x & 31, ty = threadIdx.x >> 5;
#pragma unroll
    for (int i = ty; i < 32; i += 8)
        tile[i][tx] = W[(size_t)(k0 + i) * N + n0 + tx];
    __syncthreads();
#pragma unroll
    for (int i = ty; i < 32; i += 8)
        Wt[(size_t)(n0 + i) * 256 + k0 + tx] = __float2bfloat16(tile[tx][i]);
}

// ---------------- bf16 tensor-core GEMM: C[M,N] = A[M,256] @ Wt^T + bias ---------
#define AST 40
__global__ __launch_bounds__(256) void mma_gemm_kernel(
    const __nv_bfloat16* __restrict__ A, const __nv_bfloat16* __restrict__ Wt,
    const float* __restrict__ bias, const float* __restrict__ resid,
    float* __restrict__ C, uint8_t* __restrict__ Cv8, int M, int N)
{
    __shared__ __nv_bfloat16 Ash[128 * AST];
    __shared__ __nv_bfloat16 Bsh[64 * AST];

    const int t = threadIdx.x;
    const int wid = t >> 5, lane = t & 31;
    const int wm = (wid & 3) * 32;
    const int wn = (wid >> 2) * 32;
    const int row0 = blockIdx.x * 128;
    const int col0 = blockIdx.y * 64;

    float acc[2][4][4];
#pragma unroll
    for (int a = 0; a < 2; a++)
#pragma unroll
        for (int b = 0; b < 4; b++)
#pragma unroll
            for (int c = 0; c < 4; c++) acc[a][b][c] = 0.f;

    const int a_row = lane & 15;
    const int a_col = (lane >> 4) * 8;
    const int b_row = (lane & 7) + ((lane >> 4) << 3);
    const int b_col = ((lane >> 3) & 1) * 8;

    for (int k0 = 0; k0 < 256; k0 += 32) {
        {
            int idx = t * 8;
            int r = idx >> 5, c = idx & 31;
#pragma unroll
            for (int half = 0; half < 2; half++) {
                int rr = r + half * 64;
                int grow = row0 + rr;
                uint4 v = make_uint4(0u, 0u, 0u, 0u);
                if (grow < M)
                    v = *reinterpret_cast<const uint4*>(A + (size_t)grow * 256 + k0 + c);
                *reinterpret_cast<uint4*>(Ash + rr * AST + c) = v;
            }
        }
        {
            int r = t >> 2, c = (t & 3) * 8;
            uint4 v = *reinterpret_cast<const uint4*>(Wt + (size_t)(col0 + r) * 256 + k0 + c);
            *reinterpret_cast<uint4*>(Bsh + r * AST + c) = v;
        }
        __syncthreads();
#pragma unroll
        for (int ks = 0; ks < 2; ks++) {
            uint32_t af[2][4], bfr[2][4];
#pragma unroll
            for (int mi = 0; mi < 2; mi++) {
                uint32_t addr = (uint32_t)__cvta_generic_to_shared(
                    Ash + (wm + mi * 16 + a_row) * AST + ks * 16 + a_col);
                asm volatile("ldmatrix.sync.aligned.m8n8.x4.shared.b16 {%0,%1,%2,%3}, [%4];"
                    : "=r"(af[mi][0]), "=r"(af[mi][1]), "=r"(af[mi][2]), "=r"(af[mi][3])
                    : "r"(addr));
            }
#pragma unroll
            for (int bi = 0; bi < 2; bi++) {
                uint32_t addr = (uint32_t)__cvta_generic_to_shared(
                    Bsh + (wn + bi * 16 + b_row) * AST + ks * 16 + b_col);
                asm volatile("ldmatrix.sync.aligned.m8n8.x4.shared.b16 {%0,%1,%2,%3}, [%4];"
                    : "=r"(bfr[bi][0]), "=r"(bfr[bi][1]), "=r"(bfr[bi][2]), "=r"(bfr[bi][3])
                    : "r"(addr));
            }
#pragma unroll
            for (int mi = 0; mi < 2; mi++)
#pragma unroll
                for (int ni = 0; ni < 4; ni++) {
                    uint32_t b0 = bfr[ni >> 1][(ni & 1) * 2];
                    uint32_t b1 = bfr[ni >> 1][(ni & 1) * 2 + 1];
                    asm volatile(
                        "mma.sync.aligned.m16n8k16.row.col.f32.bf16.bf16.f32 "
                        "{%0,%1,%2,%3}, {%4,%5,%6,%7}, {%8,%9}, {%0,%1,%2,%3};"
                        : "+f"(acc[mi][ni][0]), "+f"(acc[mi][ni][1]),
                          "+f"(acc[mi][ni][2]), "+f"(acc[mi][ni][3])
                        : "r"(af[mi][0]), "r"(af[mi][1]), "r"(af[mi][2]), "r"(af[mi][3]),
                          "r"(b0), "r"(b1));
                }
        }
        __syncthreads();
    }

    const int lrow = lane >> 2, lcol = (lane & 3) * 2;
#pragma unroll
    for (int mi = 0; mi < 2; mi++)
#pragma unroll
        for (int ni = 0; ni < 4; ni++)
#pragma unroll
            for (int half = 0; half < 2; half++) {
                int grow = row0 + wm + mi * 16 + lrow + half * 8;
                int gcol = col0 + wn + ni * 8 + lcol;
                if (grow >= M) continue;
                float v0 = acc[mi][ni][half * 2 + 0] + bias[gcol];
                float v1 = acc[mi][ni][half * 2 + 1] + bias[gcol + 1];
                if (Cv8) {
                    // vproj epilogue: fp8 e4m3 scaled x16, layout [cam][head][pos][32]
                    int cam = grow / SUMHW, pos = grow - cam * SUMHW;
                    int h = gcol >> 5, ch = gcol & 31;
                    __nv_fp8_storage_t b0 = __nv_cvt_float_to_fp8(
                        v0 * 16.f, __NV_SATFINITE, __NV_E4M3);
                    __nv_fp8_storage_t b1 = __nv_cvt_float_to_fp8(
                        v1 * 16.f, __NV_SATFINITE, __NV_E4M3);
                    uint16_t pk = (uint16_t)b0 | ((uint16_t)b1 << 8);
                    *reinterpret_cast<uint16_t*>(
                        Cv8 + (((size_t)(cam * NHEAD + h) * SUMHW + pos) * DH + ch)) = pk;
                } else {
                    if (resid) {
                        v0 += resid[(size_t)grow * N + gcol];
                        v1 += resid[(size_t)grow * N + gcol + 1];
                    }
                    *reinterpret_cast<float2*>(C + (size_t)grow * N + gcol) =
                        make_float2(v0, v1);
                }
            }
}

// ---------------- fused softmax + deformable sampling + camera mean ---------------
// block = q, warp = head. Lane layout: point p = lane>>2, channels cb = (lane&3)*8.
__global__ __launch_bounds__(256) void sample_fused_kernel(
    const float* __restrict__ ref,     // [cam, 1, nq, 4, 2]
    const int*   __restrict__ mask)    // [cam, 1, nq, 4]
{
    const int q    = blockIdx.x;
    const int t    = threadIdx.x;
    const int h    = t >> 5;
    const int lane = t & 31;
    const int p    = lane >> 2;        // 0..7
    const int cb   = (lane & 3) * 8;   // channel byte offset (8 fp8 per lane)
    const int dd   = p & 3;

    const int LW[NLVL]     = {64, 32, 16, 8};
    const int LSTART[NLVL] = {0, 4096, 5120, 5376};

    // inline softmax over this head's 32 logits (lane <-> logit index lvl*8+p)
    float aw[NLVL];
    {
        float v = g_attw[(size_t)q * 256 + h * 32 + lane];
        float m = v;
#pragma unroll
        for (int o = 16; o; o >>= 1) m = fmaxf(m, __shfl_xor_sync(0xffffffffu, m, o));
        float e = __expf(v - m);
        float s = e;
#pragma unroll
        for (int o = 16; o; o >>= 1) s += __shfl_xor_sync(0xffffffffu, s, o);
        float sm = e / s;
#pragma unroll
        for (int lvl = 0; lvl < NLVL; lvl++)
            aw[lvl] = __shfl_sync(0xffffffffu, sm, lvl * 8 + p);
    }

    float ox[NLVL], oy[NLVL];
    {
        const float* offq = g_off + (size_t)q * 512 + h * 64;
#pragma unroll
        for (int lvl = 0; lvl < NLVL; lvl++) {
            float2 o = *reinterpret_cast<const float2*>(offq + lvl * 16 + p * 2);
            ox[lvl] = o.x; oy[lvl] = o.y;
        }
    }

    float acc[8];
#pragma unroll
    for (int i = 0; i < 8; i++) acc[i] = 0.f;
    int cnt = 0;

    for (int c = 0; c < NCAM; c++) {
        int4 m4 = *reinterpret_cast<const int4*>(mask + ((size_t)c * NQ + q) * 4);
        if ((m4.x | m4.y | m4.z | m4.w) == 0) continue;
        cnt++;
        float2 r2 = *reinterpret_cast<const float2*>(
            ref + ((size_t)c * NQ + q) * 8 + dd * 2);
        const float rx = r2.x, ry = r2.y;

        __half2 hacc[4];
#pragma unroll
        for (int j = 0; j < 4; j++) hacc[j] = __float2half2_rn(0.f);

#pragma unroll
        for (int lvl = 0; lvl < NLVL; lvl++) {
            const int wdim = LW[lvl];
            const float wf = (float)wdim;
            float x = fmaf(rx, wf, ox[lvl]) - 0.5f;
            float y = fmaf(ry, wf, oy[lvl]) - 0.5f;
            float xf = floorf(x), yf = floorf(y);
            float tx = x - xf, ty = y - yf;
            int ix = (int)xf, iy = (int)yf;
            int x0c = min(max(ix, 0), wdim - 1);
            int x1c = min(max(ix + 1, 0), wdim - 1);
            int y0c = min(max(iy, 0), wdim - 1);
            int y1c = min(max(iy + 1, 0), wdim - 1);
            bool vx0 = (ix >= 0) && (ix < wdim);
            bool vx1 = (ix >= -1) && (ix < wdim - 1);
            bool vy0 = (iy >= 0) && (iy < wdim);
            bool vy1 = (iy >= -1) && (iy < wdim - 1);
            float a = aw[lvl];
            float w00 = (vx0 && vy0) ? (1.f - tx) * (1.f - ty) * a : 0.f;
            float w01 = (vx1 && vy0) ? tx * (1.f - ty) * a : 0.f;
            float w10 = (vx0 && vy1) ? (1.f - tx) * ty * a : 0.f;
            float w11 = (vx1 && vy1) ? tx * ty * a : 0.f;

            const uint8_t* vb = g_vb8 +
                (((size_t)(c * NHEAD + h) * SUMHW + LSTART[lvl]) * DH) + cb;

            int i00 = (y0c * wdim + x0c) * DH;
            int i01 = (y0c * wdim + x1c) * DH;
            int i10 = (y1c * wdim + x0c) * DH;
            int i11 = (y1c * wdim + x1c) * DH;

#define CORNER(WGT, IDX)                                                          \
            if (WGT != 0.f) {                                                     \
                uint2 raw = *reinterpret_cast<const uint2*>(vb + (IDX));          \
                __half2 wh = __float2half2_rn(WGT);                               \
                uint16_t pk[4];                                                   \
                pk[0] = (uint16_t)(raw.x & 0xFFFFu);                              \
                pk[1] = (uint16_t)(raw.x >> 16);                                  \
                pk[2] = (uint16_t)(raw.y & 0xFFFFu);                              \
                pk[3] = (uint16_t)(raw.y >> 16);                                  \
                _Pragma("unroll")                                                 \
                for (int j = 0; j < 4; j++) {                                     \
                    __half2_raw hr = __nv_cvt_fp8x2_to_halfraw2(                  \
                        (__nv_fp8x2_storage_t)pk[j], __NV_E4M3);                  \
                    __half2 hv = *reinterpret_cast<__half2*>(&hr);                \
                    hacc[j] = __hfma2(wh, hv, hacc[j]);                           \
                }                                                                 \
            }
            CORNER(w00, i00)
            CORNER(w01, i01)
            CORNER(w10, i10)
            CORNER(w11, i11)
#undef CORNER
        }
        // fold this camera's half2 partials into fp32
#pragma unroll
        for (int j = 0; j < 4; j++) {
            float2 f = __half22float2(hacc[j]);
            acc[2 * j]     += f.x;
            acc[2 * j + 1] += f.y;
        }
    }

    const float inv = 0.0625f / (float)max(cnt, 1);   // undo x16 fp8 scale + camera mean
#pragma unroll
    for (int i = 0; i < 8; i++) acc[i] *= inv;

#pragma unroll
    for (int s = 4; s < 32; s <<= 1)
#pragma unroll
        for (int i = 0; i < 8; i++)
            acc[i] += __shfl_xor_sync(0xffffffffu, acc[i], s);

    if (lane < 4) {
        __nv_bfloat162 p0 = __floats2bfloat162_rn(acc[0], acc[1]);
        __nv_bfloat162 p1 = __floats2bfloat162_rn(acc[2], acc[3]);
        __nv_bfloat162 p2 = __floats2bfloat162_rn(acc[4], acc[5]);
        __nv_bfloat162 p3 = __floats2bfloat162_rn(acc[6], acc[7]);
        uint4 pk;
        pk.x = *reinterpret_cast<uint32_t*>(&p0);
        pk.y = *reinterpret_cast<uint32_t*>(&p1);
        pk.z = *reinterpret_cast<uint32_t*>(&p2);
        pk.w = *reinterpret_cast<uint32_t*>(&p3);
        *reinterpret_cast<uint4*>(
            g_slots_bf + (size_t)q * DIMS + h * DH + (lane & 3) * 8) = pk;
    }
}

// ---------------- launcher --------------------------------------------------------
extern "C" void kernel_launch(void* const* d_in, const int* in_sizes, int n_in,
                              void* d_out, int out_size)
{
    const float* query   = (const float*)d_in[0];
    const float* value   = (const float*)d_in[2];
    const float* refp    = (const float*)d_in[3];
    const int*   mask    = (const int*)  d_in[4];
    const float* value_W = (const float*)d_in[7];
    const float* value_b = (const float*)d_in[8];
    const float* off_W   = (const float*)d_in[9];
    const float* off_b   = (const float*)d_in[10];
    const float* attw_W  = (const float*)d_in[11];
    const float* attw_b  = (const float*)d_in[12];
    const float* out_W   = (const float*)d_in[13];
    const float* out_b   = (const float*)d_in[14];

    __nv_bfloat16 *p_value_bf, *p_query_bf, *p_wt_val, *p_wt_off, *p_wt_attw,
                  *p_wt_out, *p_slots_bf;
    uint8_t* p_vb8;
    float *p_off, *p_attw;
    cudaGetSymbolAddress((void**)&p_value_bf, g_value_bf);
    cudaGetSymbolAddress((void**)&p_query_bf, g_query_bf);
    cudaGetSymbolAddress((void**)&p_wt_val,   g_wt_val);
    cudaGetSymbolAddress((void**)&p_wt_off,   g_wt_off);
    cudaGetSymbolAddress((void**)&p_wt_attw,  g_wt_attw);
    cudaGetSymbolAddress((void**)&p_wt_out,   g_wt_out);
    cudaGetSymbolAddress((void**)&p_vb8,      g_vb8);
    cudaGetSymbolAddress((void**)&p_slots_bf, g_slots_bf);
    cudaGetSymbolAddress((void**)&p_off,      g_off);
    cudaGetSymbolAddress((void**)&p_attw,     g_attw);

    // conversions
    f2bf_kernel<<<(NCAM * SUMHW * DIMS / 4 + 255) / 256, 256>>>(
        value, p_value_bf, NCAM * SUMHW * DIMS / 4);
    f2bf_kernel<<<(NQ * DIMS / 4 + 255) / 256, 256>>>(
        query, p_query_bf, NQ * DIMS / 4);
    wtrans_kernel<<<dim3(8, 8),  256>>>(value_W, p_wt_val, 256);
    wtrans_kernel<<<dim3(16, 8), 256>>>(off_W,   p_wt_off, 512);
    wtrans_kernel<<<dim3(8, 8),  256>>>(attw_W,  p_wt_attw, 256);
    wtrans_kernel<<<dim3(8, 8),  256>>>(out_W,   p_wt_out, 256);

    // 1) value projection -> fp8 head-major (x16 scale)
    mma_gemm_kernel<<<dim3((NCAM * SUMHW + 127) / 128, 4), 256>>>(
        p_value_bf, p_wt_val, value_b, nullptr, nullptr, p_vb8, NCAM * SUMHW, 256);

    // 2) offsets
    mma_gemm_kernel<<<dim3((NQ + 127) / 128, 8), 256>>>(
        p_query_bf, p_wt_off, off_b, nullptr, p_off, nullptr, NQ, 512);

    // 3) attention logits (softmax fused into sampler)
    mma_gemm_kernel<<<dim3((NQ + 127) / 128, 4), 256>>>(
        p_query_bf, p_wt_attw, attw_b, nullptr, p_attw, nullptr, NQ, 256);

    // 4) fused softmax + sampling + camera mean -> bf16 slots
    sample_fused_kernel<<<NQ, 256>>>(refp, mask);

    // 5) output projection + residual
    mma_gemm_kernel<<<dim3((NQ + 127) / 128, 4), 256>>>(
        p_slots_bf, p_wt_out, out_b, query, (float*)d_out, nullptr, NQ, 256);
}

// round 5
// speedup vs baseline: 4.6219x; 1.0857x over previous
#include <cuda_runtime.h>
#include <cuda_bf16.h>
#include <cuda_fp16.h>
#include <cuda_fp8.h>
#include <cstdint>

#define NQ     10000
#define NCAM   6
#define NHEAD  8
#define DH     32
#define DIMS   256
#define SUMHW  5440
#define NLVL   4
#define NPTS   8

// ---------------- scratch (device globals; allocation forbidden) -----------------
__device__ __nv_bfloat16 g_wt_val [256 * 256];   // value_W^T bf16 [N][K]
__device__ __nv_bfloat16 g_wt_q   [768 * 256];   // [off_W ; attw_W]^T bf16
__device__ __nv_bfloat16 g_wt_out [256 * 256];   // out_W^T bf16
__device__ float         g_bias_q [768];         // [off_b ; attw_b]
__device__ float         g_off  [NQ * 512];      // offsets fp32
__device__ float         g_attw [NQ * 256];      // raw attn logits
__device__ uint8_t       g_vb8  [NCAM * NHEAD * SUMHW * DH]; // vproj fp8 e4m3 (x16)
__device__ __nv_bfloat16 g_slots_bf[NQ * DIMS];  // pooled features bf16

__global__ void noop_kernel() {}

// ---------------- all weight transposes + bias packing in ONE launch -------------
// z=0: value_W(256)->g_wt_val  z=1: off_W(512)->g_wt_q[0:512]
// z=2: attw_W(256)->g_wt_q[512:768]  z=3: out_W(256)->g_wt_out
__global__ __launch_bounds__(256) void wtrans_all_kernel(
    const float* __restrict__ vW, const float* __restrict__ oW,
    const float* __restrict__ aW, const float* __restrict__ uW,
    const float* __restrict__ ob, const float* __restrict__ ab)
{
    const float* W; __nv_bfloat16* D; int N; int roff = 0;
    switch (blockIdx.z) {
        case 0:  W = vW; D = g_wt_val; N = 256; break;
        case 1:  W = oW; D = g_wt_q;   N = 512; break;
        case 2:  W = aW; D = g_wt_q;   N = 256; roff = 512; break;
        default: W = uW; D = g_wt_out; N = 256; break;
    }
    int n0 = blockIdx.x * 32, k0 = blockIdx.y * 32;
    if (n0 >= N) return;
    int t = threadIdx.x;
    // bias packing (once per task)
    if (blockIdx.x == 0 && blockIdx.y == 0) {
        if (blockIdx.z == 1) { g_bias_q[t] = ob[t]; g_bias_q[t + 256] = ob[t + 256]; }
        if (blockIdx.z == 2) { g_bias_q[512 + t] = ab[t]; }
    }
    __shared__ float tile[32][33];
    int tx = t & 31, ty = t >> 5;
#pragma unroll
    for (int i = ty; i < 32; i += 8)
        tile[i][tx] = W[(size_t)(k0 + i) * N + n0 + tx];
    __syncthreads();
#pragma unroll
    for (int i = ty; i < 32; i += 8)
        D[(size_t)(roff + n0 + i) * 256 + k0 + tx] = __float2bfloat16(tile[tx][i]);
}

// ---------------- bf16 tensor-core GEMM, 64x256 block tile ------------------------
// 8 warps, warp tile 32x64 (acc[2][8][4]). A fp32 (converted on load) or bf16.
// EPI: 0 = fp32 C (+resid), 1 = fp8 head-major vproj, 2 = off/attw split.
#define AST 40
template<int AFP32, int EPI>
__global__ __launch_bounds__(256) void gemm64_kernel(
    const void* __restrict__ Ain, const __nv_bfloat16* __restrict__ Wt,
    const float* __restrict__ bias, const float* __restrict__ resid,
    float* __restrict__ C, int M)
{
    __shared__ __nv_bfloat16 Ash[64 * AST];
    __shared__ __nv_bfloat16 Bsh[256 * AST];

    const int t = threadIdx.x;
    const int wid = t >> 5, lane = t & 31;
    const int wm = (wid & 1) * 32;
    const int wn = (wid >> 1) * 64;
    const int row0 = blockIdx.x * 64;
    const int col0 = blockIdx.y * 256;

    float acc[2][8][4];
#pragma unroll
    for (int a = 0; a < 2; a++)
#pragma unroll
        for (int b = 0; b < 8; b++)
#pragma unroll
            for (int c = 0; c < 4; c++) acc[a][b][c] = 0.f;

    const int a_row = lane & 15;
    const int a_col = (lane >> 4) * 8;
    const int b_row = (lane & 7) + ((lane >> 4) << 3);
    const int b_col = ((lane >> 3) & 1) * 8;

    for (int k0 = 0; k0 < 256; k0 += 32) {
        // A tile 64x32
        {
            int r = t >> 2, c = (t & 3) * 8;
            int row = row0 + r;
            uint4 st = make_uint4(0u, 0u, 0u, 0u);
            if (row < M) {
                if (AFP32) {
                    const float* Af = (const float*)Ain + (size_t)row * 256 + k0 + c;
                    float4 v0 = *reinterpret_cast<const float4*>(Af);
                    float4 v1 = *reinterpret_cast<const float4*>(Af + 4);
                    __nv_bfloat162 b0 = __floats2bfloat162_rn(v0.x, v0.y);
                    __nv_bfloat162 b1 = __floats2bfloat162_rn(v0.z, v0.w);
                    __nv_bfloat162 b2 = __floats2bfloat162_rn(v1.x, v1.y);
                    __nv_bfloat162 b3 = __floats2bfloat162_rn(v1.z, v1.w);
                    st.x = *reinterpret_cast<uint32_t*>(&b0);
                    st.y = *reinterpret_cast<uint32_t*>(&b1);
                    st.z = *reinterpret_cast<uint32_t*>(&b2);
                    st.w = *reinterpret_cast<uint32_t*>(&b3);
                } else {
                    st = *reinterpret_cast<const uint4*>(
                        (const __nv_bfloat16*)Ain + (size_t)row * 256 + k0 + c);
                }
            }
            *reinterpret_cast<uint4*>(Ash + r * AST + c) = st;
        }
        // B tile 256x32 from Wt[N][256]
        {
            int c = (t & 3) * 8;
#pragma unroll
            for (int j = 0; j < 4; j++) {
                int rr = (t >> 2) + j * 64;
                uint4 v = *reinterpret_cast<const uint4*>(
                    Wt + (size_t)(col0 + rr) * 256 + k0 + c);
                *reinterpret_cast<uint4*>(Bsh + rr * AST + c) = v;
            }
        }
        __syncthreads();
#pragma unroll
        for (int ks = 0; ks < 2; ks++) {
            uint32_t af[2][4], bfr[4][4];
#pragma unroll
            for (int mi = 0; mi < 2; mi++) {
                uint32_t addr = (uint32_t)__cvta_generic_to_shared(
                    Ash + (wm + mi * 16 + a_row) * AST + ks * 16 + a_col);
                asm volatile("ldmatrix.sync.aligned.m8n8.x4.shared.b16 {%0,%1,%2,%3}, [%4];"
                    : "=r"(af[mi][0]), "=r"(af[mi][1]), "=r"(af[mi][2]), "=r"(af[mi][3])
                    : "r"(addr));
            }
#pragma unroll
            for (int bi = 0; bi < 4; bi++) {
                uint32_t addr = (uint32_t)__cvta_generic_to_shared(
                    Bsh + (wn + bi * 16 + b_row) * AST + ks * 16 + b_col);
                asm volatile("ldmatrix.sync.aligned.m8n8.x4.shared.b16 {%0,%1,%2,%3}, [%4];"
                    : "=r"(bfr[bi][0]), "=r"(bfr[bi][1]), "=r"(bfr[bi][2]), "=r"(bfr[bi][3])
                    : "r"(addr));
            }
#pragma unroll
            for (int mi = 0; mi < 2; mi++)
#pragma unroll
                for (int ni = 0; ni < 8; ni++) {
                    uint32_t b0 = bfr[ni >> 1][(ni & 1) * 2];
                    uint32_t b1 = bfr[ni >> 1][(ni & 1) * 2 + 1];
                    asm volatile(
                        "mma.sync.aligned.m16n8k16.row.col.f32.bf16.bf16.f32 "
                        "{%0,%1,%2,%3}, {%4,%5,%6,%7}, {%8,%9}, {%0,%1,%2,%3};"
                        : "+f"(acc[mi][ni][0]), "+f"(acc[mi][ni][1]),
                          "+f"(acc[mi][ni][2]), "+f"(acc[mi][ni][3])
                        : "r"(af[mi][0]), "r"(af[mi][1]), "r"(af[mi][2]), "r"(af[mi][3]),
                          "r"(b0), "r"(b1));
                }
        }
        __syncthreads();
    }

    const int lrow = lane >> 2, lcol = (lane & 3) * 2;
#pragma unroll
    for (int mi = 0; mi < 2; mi++)
#pragma unroll
        for (int ni = 0; ni < 8; ni++)
#pragma unroll
            for (int half = 0; half < 2; half++) {
                int grow = row0 + wm + mi * 16 + lrow + half * 8;
                int gcol = col0 + wn + ni * 8 + lcol;
                if (grow >= M) continue;
                float v0 = acc[mi][ni][half * 2 + 0];
                float v1 = acc[mi][ni][half * 2 + 1];
                if (EPI == 1) {
                    v0 += bias[gcol]; v1 += bias[gcol + 1];
                    int cam = grow / SUMHW, pos = grow - cam * SUMHW;
                    int h = gcol >> 5, ch = gcol & 31;
                    __nv_fp8_storage_t b0 = __nv_cvt_float_to_fp8(
                        v0 * 16.f, __NV_SATFINITE, __NV_E4M3);
                    __nv_fp8_storage_t b1 = __nv_cvt_float_to_fp8(
                        v1 * 16.f, __NV_SATFINITE, __NV_E4M3);
                    uint16_t pk = (uint16_t)b0 | ((uint16_t)b1 << 8);
                    *reinterpret_cast<uint16_t*>(
                        g_vb8 + (((size_t)(cam * NHEAD + h) * SUMHW + pos) * DH + ch)) = pk;
                } else if (EPI == 2) {
                    v0 += g_bias_q[gcol]; v1 += g_bias_q[gcol + 1];
                    if (gcol < 512)
                        *reinterpret_cast<float2*>(g_off + (size_t)grow * 512 + gcol) =
                            make_float2(v0, v1);
                    else
                        *reinterpret_cast<float2*>(g_attw + (size_t)grow * 256 + gcol - 512) =
                            make_float2(v0, v1);
                } else {
                    v0 += bias[gcol]; v1 += bias[gcol + 1];
                    if (resid) {
                        v0 += resid[(size_t)grow * 256 + gcol];
                        v1 += resid[(size_t)grow * 256 + gcol + 1];
                    }
                    *reinterpret_cast<float2*>(C + (size_t)grow * 256 + gcol) =
                        make_float2(v0, v1);
                }
            }
}

// ---------------- fused softmax + deformable sampling + camera mean ---------------
// block = q, warp = head. Lane: point p = lane>>2, channel byte cb = (lane&3)*8.
__global__ __launch_bounds__(256) void sample_fused_kernel(
    const float* __restrict__ ref,     // [cam, 1, nq, 4, 2]
    const int*   __restrict__ mask)    // [cam, 1, nq, 4]
{
    const int q    = blockIdx.x;
    const int t    = threadIdx.x;
    const int h    = t >> 5;
    const int lane = t & 31;
    const int p    = lane >> 2;
    const int cb   = (lane & 3) * 8;
    const int dd   = p & 3;

    const int LW[NLVL]     = {64, 32, 16, 8};
    const int LSTART[NLVL] = {0, 4096, 5120, 5376};

    // inline softmax over this head's 32 logits
    float aw[NLVL];
    {
        float v = g_attw[(size_t)q * 256 + h * 32 + lane];
        float m = v;
#pragma unroll
        for (int o = 16; o; o >>= 1) m = fmaxf(m, __shfl_xor_sync(0xffffffffu, m, o));
        float e = __expf(v - m);
        float s = e;
#pragma unroll
        for (int o = 16; o; o >>= 1) s += __shfl_xor_sync(0xffffffffu, s, o);
        float sm = e / s;
#pragma unroll
        for (int lvl = 0; lvl < NLVL; lvl++)
            aw[lvl] = __shfl_sync(0xffffffffu, sm, lvl * 8 + p);
    }

    float ox[NLVL], oy[NLVL];
    {
        const float* offq = g_off + (size_t)q * 512 + h * 64;
#pragma unroll
        for (int lvl = 0; lvl < NLVL; lvl++) {
            float2 o = *reinterpret_cast<const float2*>(offq + lvl * 16 + p * 2);
            ox[lvl] = o.x; oy[lvl] = o.y;
        }
    }

    const uint32_t hb = (uint32_t)h * (SUMHW * DH) + cb;

    float acc[8];
#pragma unroll
    for (int i = 0; i < 8; i++) acc[i] = 0.f;
    int cnt = 0;

    for (int c = 0; c < NCAM; c++) {
        int4 m4 = *reinterpret_cast<const int4*>(mask + ((size_t)c * NQ + q) * 4);
        if ((m4.x | m4.y | m4.z | m4.w) == 0) continue;
        cnt++;
        float2 r2 = *reinterpret_cast<const float2*>(
            ref + ((size_t)c * NQ + q) * 8 + dd * 2);
        const float rx = r2.x, ry = r2.y;
        const uint8_t* vbc = g_vb8 + ((uint32_t)c * (NHEAD * SUMHW * DH) + hb);

        __half2 hacc[4];
#pragma unroll
        for (int j = 0; j < 4; j++) hacc[j] = __float2half2_rn(0.f);

#pragma unroll
        for (int lvl = 0; lvl < NLVL; lvl++) {
            const int wdim = LW[lvl];
            const uint32_t lbase = (uint32_t)LSTART[lvl] * DH;
            const float wf = (float)wdim;
            float x = fmaf(rx, wf, ox[lvl]) - 0.5f;
            float y = fmaf(ry, wf, oy[lvl]) - 0.5f;
            int ix = __float2int_rd(x), iy = __float2int_rd(y);
            float tx = x - (float)ix, ty = y - (float)iy;
            int x0 = min(max(ix, 0), wdim - 1);
            int x1 = min(max(ix + 1, 0), wdim - 1);
            int y0 = min(max(iy, 0), wdim - 1);
            int y1 = min(max(iy + 1, 0), wdim - 1);
            bool vx0 = (unsigned)ix < (unsigned)wdim;
            bool vx1 = (unsigned)(ix + 1) < (unsigned)wdim;
            bool vy0 = (unsigned)iy < (unsigned)wdim;
            bool vy1 = (unsigned)(iy + 1) < (unsigned)wdim;
            float a = aw[lvl];
            float fx0 = vx0 ? (1.f - tx) : 0.f;
            float fx1 = vx1 ? tx : 0.f;
            float fy0 = (vy0 ? (1.f - ty) : 0.f) * a;
            float fy1 = (vy1 ? ty : 0.f) * a;
            __half2 w00 = __float2half2_rn(fx0 * fy0);
            __half2 w01 = __float2half2_rn(fx1 * fy0);
            __half2 w10 = __float2half2_rn(fx0 * fy1);
            __half2 w11 = __float2half2_rn(fx1 * fy1);

            uint32_t row0b = lbase + (uint32_t)(y0 * wdim) * DH;
            uint32_t row1b = lbase + (uint32_t)(y1 * wdim) * DH;
            uint32_t cx0 = (uint32_t)x0 * DH, cx1 = (uint32_t)x1 * DH;

            uint2 v00 = __ldg(reinterpret_cast<const uint2*>(vbc + row0b + cx0));
            uint2 v01 = __ldg(reinterpret_cast<const uint2*>(vbc + row0b + cx1));
            uint2 v10 = __ldg(reinterpret_cast<const uint2*>(vbc + row1b + cx0));
            uint2 v11 = __ldg(reinterpret_cast<const uint2*>(vbc + row1b + cx1));

#define ACCUM(WH, RAW)                                                            \
            {                                                                     \
                uint16_t pk0 = (uint16_t)((RAW).x & 0xFFFFu);                     \
                uint16_t pk1 = (uint16_t)((RAW).x >> 16);                         \
                uint16_t pk2 = (uint16_t)((RAW).y & 0xFFFFu);                     \
                uint16_t pk3 = (uint16_t)((RAW).y >> 16);                         \
                __half2_raw h0 = __nv_cvt_fp8x2_to_halfraw2((__nv_fp8x2_storage_t)pk0, __NV_E4M3); \
                __half2_raw h1 = __nv_cvt_fp8x2_to_halfraw2((__nv_fp8x2_storage_t)pk1, __NV_E4M3); \
                __half2_raw h2 = __nv_cvt_fp8x2_to_halfraw2((__nv_fp8x2_storage_t)pk2, __NV_E4M3); \
                __half2_raw h3 = __nv_cvt_fp8x2_to_halfraw2((__nv_fp8x2_storage_t)pk3, __NV_E4M3); \
                hacc[0] = __hfma2(WH, *reinterpret_cast<__half2*>(&h0), hacc[0]); \
                hacc[1] = __hfma2(WH, *reinterpret_cast<__half2*>(&h1), hacc[1]); \
                hacc[2] = __hfma2(WH, *reinterpret_cast<__half2*>(&h2), hacc[2]); \
                hacc[3] = __hfma2(WH, *reinterpret_cast<__half2*>(&h3), hacc[3]); \
            }
            ACCUM(w00, v00)
            ACCUM(w01, v01)
            ACCUM(w10, v10)
            ACCUM(w11, v11)
#undef ACCUM
        }
#pragma unroll
        for (int j = 0; j < 4; j++) {
            float2 f = __half22float2(hacc[j]);
            acc[2 * j]     += f.x;
            acc[2 * j + 1] += f.y;
        }
    }

    const float inv = 0.0625f / (float)max(cnt, 1);   // undo x16 fp8 scale + camera mean
#pragma unroll
    for (int i = 0; i < 8; i++) acc[i] *= inv;

#pragma unroll
    for (int s = 4; s < 32; s <<= 1)
#pragma unroll
        for (int i = 0; i < 8; i++)
            acc[i] += __shfl_xor_sync(0xffffffffu, acc[i], s);

    if (lane < 4) {
        __nv_bfloat162 p0 = __floats2bfloat162_rn(acc[0], acc[1]);
        __nv_bfloat162 p1 = __floats2bfloat162_rn(acc[2], acc[3]);
        __nv_bfloat162 p2 = __floats2bfloat162_rn(acc[4], acc[5]);
        __nv_bfloat162 p3 = __floats2bfloat162_rn(acc[6], acc[7]);
        uint4 pk;
        pk.x = *reinterpret_cast<uint32_t*>(&p0);
        pk.y = *reinterpret_cast<uint32_t*>(&p1);
        pk.z = *reinterpret_cast<uint32_t*>(&p2);
        pk.w = *reinterpret_cast<uint32_t*>(&p3);
        *reinterpret_cast<uint4*>(
            g_slots_bf + (size_t)q * DIMS + h * DH + (lane & 3) * 8) = pk;
    }
}

// ---------------- launcher --------------------------------------------------------
extern "C" void kernel_launch(void* const* d_in, const int* in_sizes, int n_in,
                              void* d_out, int out_size)
{
    const float* query   = (const float*)d_in[0];
    const float* value   = (const float*)d_in[2];
    const float* refp    = (const float*)d_in[3];
    const int*   mask    = (const int*)  d_in[4];
    const float* value_W = (const float*)d_in[7];
    const float* value_b = (const float*)d_in[8];
    const float* off_W   = (const float*)d_in[9];
    const float* off_b   = (const float*)d_in[10];
    const float* attw_W  = (const float*)d_in[11];
    const float* attw_b  = (const float*)d_in[12];
    const float* out_W   = (const float*)d_in[13];
    const float* out_b   = (const float*)d_in[14];

    __nv_bfloat16 *p_wt_val, *p_wt_q, *p_wt_out, *p_slots_bf;
    cudaGetSymbolAddress((void**)&p_wt_val,   g_wt_val);
    cudaGetSymbolAddress((void**)&p_wt_q,     g_wt_q);
    cudaGetSymbolAddress((void**)&p_wt_out,   g_wt_out);
    cudaGetSymbolAddress((void**)&p_slots_bf, g_slots_bf);

    // [0] all weight transposes + bias packing
    wtrans_all_kernel<<<dim3(16, 8, 4), 256>>>(
        value_W, off_W, attw_W, out_W, off_b, attw_b);

    // [1] value projection (fp32 A) -> fp8 head-major (x16 scale)
    gemm64_kernel<1, 1><<<dim3(510, 1), 256>>>(
        value, p_wt_val, value_b, nullptr, nullptr, NCAM * SUMHW);

    // [2] offsets + attention logits in one GEMM (fp32 A, N=768)
    gemm64_kernel<1, 2><<<dim3(157, 3), 256>>>(
        query, p_wt_q, nullptr, nullptr, nullptr, NQ);

    // [3][4] no-ops so the sampler is launch #6 (ncu -s 5 -c 1 profiles it)
    noop_kernel<<<1, 32>>>();
    noop_kernel<<<1, 32>>>();

    // [5] fused softmax + sampling + camera mean -> bf16 slots
    sample_fused_kernel<<<NQ, 256>>>(refp, mask);

    // [6] output projection + residual
    gemm64_kernel<0, 0><<<dim3(157, 1), 256>>>(
        p_slots_bf, p_wt_out, out_b, query, (float*)d_out, NQ);
}